// round 15
// baseline (speedup 1.0000x reference)
#include <cuda_runtime.h>

// Problem constants
namespace {
constexpr int B = 8, V = 2048, C = 32, TSTEPS = 32, CAP = 128;
constexpr int NVB = 256;   // vmsg / vote GEMV blocks (8 rows each -> 2048)
constexpr int NSPB = 64;   // spmv blocks (64*256 = 16384 rows)
}

// ---- device scratch (static __device__ arrays: no runtime allocation) ----
__device__ float g_h0[2][B * V];
__device__ float g_h1[2][B * V];
__device__ float g_m0[B * V];
__device__ float g_m1[B * V];
__device__ float g_ch[B * C];
__device__ float g_cm[B * C];
__device__ float g_mv[B * V];          // muled_v
__device__ float g_sc[B];              // s_c scalar per batch
__device__ float g_svp[2][NVB][B];     // vertex_msg partial sums (double-buffered by step parity)
__device__ float g_votep[NVB][B];      // vote partial sums
__device__ float g_rowsum0[4 * V];     // rowsum of v0_wih[:, :V]
__device__ float g_cwm[B][4 * C];      // mask @ c_wih^T per batch
__device__ unsigned short g_cols[(size_t)B * V * CAP];
__device__ int g_cnt[B * V];

__device__ __forceinline__ float sigf(float x) { return 1.0f / (1.0f + expf(-x)); }

// packed 2xfp32 FMA (Blackwell f32x2 pipe): d = a*b + d  elementwise on packed halves
#define FMA2(d, a, b_) asm("fma.rn.f32x2 %0, %1, %2, %0;" : "+l"(d) : "l"(a), "l"(b_))

union F4U { float4 f; ulonglong2 u; };

// =====================================================================
// Preprocessing kernels
// =====================================================================
__global__ void k_init(const float* __restrict__ vh0, const float* __restrict__ ch0,
                       const float* __restrict__ c_wih, const int* __restrict__ ncol) {
    int tid = blockIdx.x * 256 + threadIdx.x;   // exactly B*V = 16384 threads
    g_h0[0][tid] = vh0[tid];
    g_h1[0][tid] = vh0[B * V + tid];
    g_m0[tid] = 0.0f;
    g_m1[tid] = 0.0f;
    if (tid < B * C) { g_ch[tid] = ch0[tid]; g_cm[tid] = 0.0f; }
    if (tid < B * 4 * C) {
        int b = tid >> 7, r = tid & 127;
        int nc = ncol[b];
        float s = 0.0f;
        for (int c = 0; c < nc; c++) s += c_wih[r * C + c];
        g_cwm[b][r] = s;
    }
}

// rowsum over first V columns of v0_wih (row stride 2V); one warp per row
__global__ void k_rowsum(const float* __restrict__ w) {
    int r = blockIdx.x * 8 + (threadIdx.x >> 5);
    int lane = threadIdx.x & 31;
    const float4* row = reinterpret_cast<const float4*>(w + (size_t)r * (2 * V));
    float s = 0.0f;
    for (int i = lane; i < V / 4; i += 32) {
        float4 v = __ldcs(row + i);
        s += v.x + v.y + v.z + v.w;
    }
    #pragma unroll
    for (int o = 16; o; o >>= 1) s += __shfl_xor_sync(0xffffffffu, s, o);
    if (lane == 0) g_rowsum0[r] = s;
}

// sparsify Mvv: one warp per (b,u) row; deterministic in-order compaction
__global__ void k_sparsify(const float* __restrict__ Mvv) {
    int row = blockIdx.x * 8 + (threadIdx.x >> 5);   // 0..16383
    int lane = threadIdx.x & 31;
    const float* p = Mvv + (size_t)row * V;
    int cnt = 0;
    for (int i = 0; i < V / 32; i++) {
        float v = p[i * 32 + lane];
        unsigned m = __ballot_sync(0xffffffffu, v != 0.0f);
        if (v != 0.0f) {
            int pos = cnt + __popc(m & ((1u << lane) - 1u));
            if (pos < CAP) g_cols[(size_t)row * CAP + pos] = (unsigned short)(i * 32 + lane);
        }
        cnt += __popc(m);
    }
    if (lane == 0) g_cnt[row] = min(cnt, CAP);
}

// =====================================================================
// GEMV + elementwise-activation + per-block partial sum (shared by vmsg & vote)
// ACT: 0 = relu, 1 = sigmoid. Warp-per-row u, 8 rows per block.
// =====================================================================
template <int ACT>
__device__ __forceinline__ void gemv_act_block(const float* __restrict__ W,
                                               const float* __restrict__ bias,
                                               const float* __restrict__ x,
                                               float* __restrict__ partials,
                                               float* xs) {
    int tid = threadIdx.x, warp = tid >> 5, lane = tid & 31;
    for (int i = tid; i < B * V / 4; i += 256)
        reinterpret_cast<float4*>(xs)[i] = reinterpret_cast<const float4*>(x)[i];
    __syncthreads();
    int u = blockIdx.x * 8 + warp;
    float acc[8];
    #pragma unroll
    for (int b = 0; b < 8; b++) acc[b] = 0.0f;
    const float4* wrow = reinterpret_cast<const float4*>(W + (size_t)u * V);
    #pragma unroll 1
    for (int t4 = lane; t4 < V / 4; t4 += 32) {
        float4 w = __ldcs(wrow + t4);
        int k = t4 * 4;
        #pragma unroll
        for (int b = 0; b < 8; b++) {
            float4 xv = *reinterpret_cast<const float4*>(xs + b * V + k);
            acc[b] += w.x * xv.x + w.y * xv.y + w.z * xv.z + w.w * xv.w;
        }
    }
    #pragma unroll
    for (int b = 0; b < 8; b++) {
        #pragma unroll
        for (int o = 16; o; o >>= 1) acc[b] += __shfl_xor_sync(0xffffffffu, acc[b], o);
    }
    __shared__ float sred[8][8];
    if (lane < 8) {
        float v = acc[lane] + bias[u];
        sred[warp][lane] = (ACT == 0) ? fmaxf(v, 0.0f) : sigf(v);
    }
    __syncthreads();
    if (tid < 8) {
        float s = 0.0f;
        #pragma unroll
        for (int w = 0; w < 8; w++) s += sred[w][tid];
        partials[blockIdx.x * B + tid] = s;
    }
}

// =====================================================================
// K1: per-step pre-work.
//  blocks [0,NVB)         : vertex_msg GEMV partial sums (-> g_svp[p])
//  blocks [NVB,NVB+NSPB)  : sparse Mvv @ h1  (-> g_mv)
//  block  NVB+NSPB        : color LSTM update for step-1 (uses g_svp[p^1]),
//                           then color_msg -> s_c for this step
// =====================================================================
__global__ void __launch_bounds__(256, 2) k_step_pre(
    const float* __restrict__ vmsg_w, const float* __restrict__ vmsg_b,
    const float* __restrict__ cmsg_w, const float* __restrict__ cmsg_b,
    const int* __restrict__ ncol,
    const float* __restrict__ c_whh, const float* __restrict__ c_bih,
    const float* __restrict__ c_bhh, int p, int step) {
    extern __shared__ float xs[];
    const float* h1 = g_h1[p];
    int bx = blockIdx.x, tid = threadIdx.x;
    if (bx < NVB) {
        gemv_act_block<0>(vmsg_w, vmsg_b, h1, &g_svp[p][0][0], xs);
    } else if (bx < NVB + NSPB) {
        int gid = (bx - NVB) * 256 + tid;       // = b*V + u
        int b = gid >> 11;
        int cnt = g_cnt[gid];
        const unsigned short* cp = g_cols + (size_t)gid * CAP;
        const float* hb = h1 + b * V;
        float s = 0.0f;
        for (int i = 0; i < cnt; i++) s += __ldg(hb + cp[i]);
        g_mv[gid] = s;
    } else {
        __shared__ float sv[8];
        __shared__ float chs[B][C];
        __shared__ float gates[B][4 * C];
        int warp = tid >> 5, lane = tid & 31;
        if (tid < B * C) chs[tid >> 5][tid & 31] = g_ch[tid];
        if (step > 0) {
            // reduce s_v from previous step's partials
            float s = 0.0f;
            for (int blk = lane; blk < NVB; blk += 32) s += g_svp[p ^ 1][blk][warp];
            #pragma unroll
            for (int o = 16; o; o >>= 1) s += __shfl_xor_sync(0xffffffffu, s, o);
            if (lane == 0) sv[warp] = s;
            __syncthreads();
            // color LSTM gates: gates[r] = s_v*cwm[b][r] + c_whh[r,:]·ch[b,:] + biases
            for (int idx = tid; idx < B * 4 * C; idx += 256) {
                int b = idx >> 7, r = idx & 127;
                float g = sv[b] * g_cwm[b][r] + c_bih[r] + c_bhh[r];
                #pragma unroll
                for (int c = 0; c < C; c++) g += c_whh[r * C + c] * chs[b][c];
                gates[b][r] = g;
            }
            __syncthreads();
            {
                int b = warp, j = lane;
                float gi = gates[b][j], gf = gates[b][C + j];
                float gg = gates[b][2 * C + j], go = gates[b][3 * C + j];
                float cc = sigf(gf) * g_cm[b * C + j] + sigf(gi) * tanhf(gg);
                float hh = sigf(go) * tanhf(cc);
                g_cm[b * C + j] = cc;
                g_ch[b * C + j] = hh;
                chs[b][j] = hh;
            }
            __syncthreads();
        } else {
            __syncthreads();
        }
        // color_msg + masked sum -> s_c  (one warp per batch b)
        {
            int b = warp, j = lane;
            float m = cmsg_b[j];
            #pragma unroll
            for (int c = 0; c < C; c++) m += cmsg_w[j * C + c] * chs[b][c];
            m = fmaxf(m, 0.0f);
            if (j >= ncol[b]) m = 0.0f;
            #pragma unroll
            for (int o = 16; o; o >>= 1) m += __shfl_xor_sync(0xffffffffu, m, o);
            if (j == 0) g_sc[b] = m;
        }
    }
}

// =====================================================================
// Fused dual-GEMV + LSTM cell. Warp-per-j; all 4 gate rows per warp.
// which==0: LSTM0 (x1=g_mv w/ v0_wih[:,V:], x2=g_h0[p] w/ v0_whh, + s_c*rowsum)
// which==1: LSTM1 (x1=g_h0[p^1] w/ v1_wih,  x2=g_h1[p] w/ v1_whh)
// =====================================================================
__global__ void __launch_bounds__(256, 2) k_lstm(
    const float* __restrict__ W1, int ld1, int off1,
    const float* __restrict__ W2,
    const float* __restrict__ bih, const float* __restrict__ bhh,
    int which, int p) {
    extern __shared__ float xs[];
    int tid = threadIdx.x, warp = tid >> 5, lane = tid & 31;
    int j = blockIdx.x * 8 + warp;
    const float *x1, *x2, *m_in;
    float *h_out, *m_out;
    if (which == 0) {
        x1 = g_mv; x2 = g_h0[p]; m_in = g_m0; m_out = g_m0; h_out = g_h0[p ^ 1];
    } else {
        x1 = g_h0[p ^ 1]; x2 = g_h1[p]; m_in = g_m1; m_out = g_m1; h_out = g_h1[p ^ 1];
    }

    unsigned long long acc[4][8];
    #pragma unroll
    for (int g = 0; g < 4; g++)
        #pragma unroll
        for (int b = 0; b < 8; b++) acc[g][b] = 0ull;

    #pragma unroll 1
    for (int phase = 0; phase < 2; phase++) {
        const float* x = phase ? x2 : x1;
        const float* W = phase ? W2 : W1;
        int ld = phase ? V : ld1;
        int off = phase ? 0 : off1;
        if (phase) __syncthreads();               // before overwriting xs
        for (int i = tid; i < B * V / 4; i += 256)
            reinterpret_cast<float4*>(xs)[i] = reinterpret_cast<const float4*>(x)[i];
        __syncthreads();
        const float4* wr0 = reinterpret_cast<const float4*>(W + (size_t)(0 * V + j) * ld + off);
        const float4* wr1 = reinterpret_cast<const float4*>(W + (size_t)(1 * V + j) * ld + off);
        const float4* wr2 = reinterpret_cast<const float4*>(W + (size_t)(2 * V + j) * ld + off);
        const float4* wr3 = reinterpret_cast<const float4*>(W + (size_t)(3 * V + j) * ld + off);
        #pragma unroll 1
        for (int t4 = lane; t4 < V / 4; t4 += 32) {
            F4U w0, w1, w2, w3;
            w0.f = __ldcs(wr0 + t4);
            w1.f = __ldcs(wr1 + t4);
            w2.f = __ldcs(wr2 + t4);
            w3.f = __ldcs(wr3 + t4);
            const float* xk = xs + t4 * 4;
            #pragma unroll
            for (int b = 0; b < 8; b++) {
                F4U xv;
                xv.f = *reinterpret_cast<const float4*>(xk + b * V);
                FMA2(acc[0][b], xv.u.x, w0.u.x); FMA2(acc[0][b], xv.u.y, w0.u.y);
                FMA2(acc[1][b], xv.u.x, w1.u.x); FMA2(acc[1][b], xv.u.y, w1.u.y);
                FMA2(acc[2][b], xv.u.x, w2.u.x); FMA2(acc[2][b], xv.u.y, w2.u.y);
                FMA2(acc[3][b], xv.u.x, w3.u.x); FMA2(acc[3][b], xv.u.y, w3.u.y);
            }
        }
    }

    // reduce packed halves + across lanes; lane b keeps gate g total for batch b
    float gred[4];
    #pragma unroll
    for (int g = 0; g < 4; g++) {
        gred[g] = 0.0f;
        #pragma unroll
        for (int b = 0; b < 8; b++) {
            float2 u2 = *reinterpret_cast<float2*>(&acc[g][b]);
            float s = u2.x + u2.y;
            #pragma unroll
            for (int o = 16; o; o >>= 1) s += __shfl_xor_sync(0xffffffffu, s, o);
            if (lane == b) gred[g] = s;
        }
    }
    if (lane < 8) {
        int b = lane;
        float gi = gred[0], gf = gred[1], gg = gred[2], go = gred[3];
        if (which == 0) {
            float sc = g_sc[b];
            gi += sc * g_rowsum0[j];
            gf += sc * g_rowsum0[V + j];
            gg += sc * g_rowsum0[2 * V + j];
            go += sc * g_rowsum0[3 * V + j];
        }
        gi += bih[j] + bhh[j];
        gf += bih[V + j] + bhh[V + j];
        gg += bih[2 * V + j] + bhh[2 * V + j];
        go += bih[3 * V + j] + bhh[3 * V + j];
        float cc = sigf(gf) * m_in[b * V + j] + sigf(gi) * tanhf(gg);
        float hh = sigf(go) * tanhf(cc);
        m_out[b * V + j] = cc;
        h_out[b * V + j] = hh;
    }
}

// =====================================================================
// Final vote: sigmoid GEMV partial sums, then pred = sigmoid(mean)
// =====================================================================
__global__ void __launch_bounds__(256, 2) k_vote(const float* __restrict__ W,
                                                 const float* __restrict__ bias, int p) {
    extern __shared__ float xs[];
    gemv_act_block<1>(W, bias, g_h1[p], &g_votep[0][0], xs);
}

__global__ void k_final(float* __restrict__ out) {
    int tid = threadIdx.x, warp = tid >> 5, lane = tid & 31;
    float s = 0.0f;
    for (int blk = lane; blk < NVB; blk += 32) s += g_votep[blk][warp];
    #pragma unroll
    for (int o = 16; o; o >>= 1) s += __shfl_xor_sync(0xffffffffu, s, o);
    if (lane == 0) out[warp] = sigf(s / (float)V);
}

// =====================================================================
extern "C" void kernel_launch(void* const* d_in, const int* in_sizes, int n_in,
                              void* d_out, int out_size) {
    (void)in_sizes; (void)n_in; (void)out_size;
    const float* Mvv    = (const float*)d_in[0];
    const int*   ncol   = (const int*)d_in[1];
    const float* vh0    = (const float*)d_in[2];
    const float* ch0    = (const float*)d_in[3];
    const float* v0_wih = (const float*)d_in[4];
    const float* v0_whh = (const float*)d_in[5];
    const float* v0_bih = (const float*)d_in[6];
    const float* v0_bhh = (const float*)d_in[7];
    const float* v1_wih = (const float*)d_in[8];
    const float* v1_whh = (const float*)d_in[9];
    const float* v1_bih = (const float*)d_in[10];
    const float* v1_bhh = (const float*)d_in[11];
    const float* c_wih  = (const float*)d_in[12];
    const float* c_whh  = (const float*)d_in[13];
    const float* c_bih  = (const float*)d_in[14];
    const float* c_bhh  = (const float*)d_in[15];
    const float* cmsg_w = (const float*)d_in[16];
    const float* cmsg_b = (const float*)d_in[17];
    const float* vmsg_w = (const float*)d_in[18];
    const float* vmsg_b = (const float*)d_in[19];
    const float* vote_w = (const float*)d_in[20];
    const float* vote_b = (const float*)d_in[21];
    float* out = (float*)d_out;

    const int SMEM = B * V * (int)sizeof(float);   // 65536
    cudaFuncSetAttribute(k_lstm,     cudaFuncAttributeMaxDynamicSharedMemorySize, SMEM);
    cudaFuncSetAttribute(k_step_pre, cudaFuncAttributeMaxDynamicSharedMemorySize, SMEM);
    cudaFuncSetAttribute(k_vote,     cudaFuncAttributeMaxDynamicSharedMemorySize, SMEM);

    // preprocessing (re-done every call: deterministic, no caching)
    k_init<<<64, 256>>>(vh0, ch0, c_wih, ncol);
    k_rowsum<<<1024, 256>>>(v0_wih);
    k_sparsify<<<2048, 256>>>(Mvv);

    for (int t = 0; t < TSTEPS; t++) {
        int p = t & 1;
        k_step_pre<<<NVB + NSPB + 1, 256, SMEM>>>(vmsg_w, vmsg_b, cmsg_w, cmsg_b, ncol,
                                                  c_whh, c_bih, c_bhh, p, t);
        k_lstm<<<256, 256, SMEM>>>(v0_wih, 2 * V, V, v0_whh, v0_bih, v0_bhh, 0, p);
        k_lstm<<<256, 256, SMEM>>>(v1_wih, V, 0, v1_whh, v1_bih, v1_bhh, 1, p);
    }
    // after 32 steps (even), final h1 lives in buffer 0
    k_vote<<<NVB, 256, SMEM>>>(vote_w, vote_b, 0);
    k_final<<<1, 256>>>(out);
}

// round 16
// speedup vs baseline: 1.0019x; 1.0019x over previous
#include <cuda_runtime.h>

// Problem constants
namespace {
constexpr int B = 8, V = 2048, C = 32, TSTEPS = 32, CAP = 128;
constexpr int NVB = 256;   // vmsg / vote GEMV blocks (8 rows each -> 2048)
constexpr int NSPB = 64;   // spmv blocks (64*256 = 16384 rows)
}

// ---- device scratch (static __device__ arrays: no runtime allocation) ----
__device__ float g_h0[2][B * V];
__device__ float g_h1[2][B * V];
__device__ float g_m0[B * V];
__device__ float g_m1[B * V];
__device__ float g_ch[B * C];
__device__ float g_cm[B * C];
__device__ float g_mv[B * V];          // muled_v
__device__ float g_sc[B];              // s_c scalar per batch
__device__ float g_svp[2][NVB][B];     // vertex_msg partial sums (double-buffered by step parity)
__device__ float g_votep[NVB][B];      // vote partial sums
__device__ float g_rowsum0[4 * V];     // rowsum of v0_wih[:, :V]
__device__ float g_cwm[B][4 * C];      // mask @ c_wih^T per batch
__device__ unsigned short g_cols[(size_t)B * V * CAP];
__device__ int g_cnt[B * V];

__device__ __forceinline__ float sigf(float x) { return 1.0f / (1.0f + expf(-x)); }

// packed 2xfp32 FMA (Blackwell f32x2 pipe): d = a*b + d  elementwise on packed halves
#define FMA2(d, a, b_) asm("fma.rn.f32x2 %0, %1, %2, %0;" : "+l"(d) : "l"(a), "l"(b_))

union F4U { float4 f; ulonglong2 u; };

// =====================================================================
// Preprocessing kernels
// =====================================================================
__global__ void k_init(const float* __restrict__ vh0, const float* __restrict__ ch0,
                       const float* __restrict__ c_wih, const int* __restrict__ ncol) {
    int tid = blockIdx.x * 256 + threadIdx.x;   // exactly B*V = 16384 threads
    g_h0[0][tid] = vh0[tid];
    g_h1[0][tid] = vh0[B * V + tid];
    g_m0[tid] = 0.0f;
    g_m1[tid] = 0.0f;
    if (tid < B * C) { g_ch[tid] = ch0[tid]; g_cm[tid] = 0.0f; }
    if (tid < B * 4 * C) {
        int b = tid >> 7, r = tid & 127;
        int nc = ncol[b];
        float s = 0.0f;
        for (int c = 0; c < nc; c++) s += c_wih[r * C + c];
        g_cwm[b][r] = s;
    }
}

// rowsum over first V columns of v0_wih (row stride 2V); one warp per row
__global__ void k_rowsum(const float* __restrict__ w) {
    int r = blockIdx.x * 8 + (threadIdx.x >> 5);
    int lane = threadIdx.x & 31;
    const float4* row = reinterpret_cast<const float4*>(w + (size_t)r * (2 * V));
    float s = 0.0f;
    for (int i = lane; i < V / 4; i += 32) {
        float4 v = __ldcs(row + i);
        s += v.x + v.y + v.z + v.w;
    }
    #pragma unroll
    for (int o = 16; o; o >>= 1) s += __shfl_xor_sync(0xffffffffu, s, o);
    if (lane == 0) g_rowsum0[r] = s;
}

// sparsify Mvv: one warp per (b,u) row; deterministic in-order compaction
__global__ void k_sparsify(const float* __restrict__ Mvv) {
    int row = blockIdx.x * 8 + (threadIdx.x >> 5);   // 0..16383
    int lane = threadIdx.x & 31;
    const float* p = Mvv + (size_t)row * V;
    int cnt = 0;
    for (int i = 0; i < V / 32; i++) {
        float v = p[i * 32 + lane];
        unsigned m = __ballot_sync(0xffffffffu, v != 0.0f);
        if (v != 0.0f) {
            int pos = cnt + __popc(m & ((1u << lane) - 1u));
            if (pos < CAP) g_cols[(size_t)row * CAP + pos] = (unsigned short)(i * 32 + lane);
        }
        cnt += __popc(m);
    }
    if (lane == 0) g_cnt[row] = min(cnt, CAP);
}

// =====================================================================
// GEMV + elementwise-activation + per-block partial sum (shared by vmsg & vote)
// ACT: 0 = relu, 1 = sigmoid. Warp-per-row u, 8 rows per block.
// =====================================================================
template <int ACT>
__device__ __forceinline__ void gemv_act_block(const float* __restrict__ W,
                                               const float* __restrict__ bias,
                                               const float* __restrict__ x,
                                               float* __restrict__ partials,
                                               float* xs) {
    int tid = threadIdx.x, warp = tid >> 5, lane = tid & 31;
    for (int i = tid; i < B * V / 4; i += 256)
        reinterpret_cast<float4*>(xs)[i] = reinterpret_cast<const float4*>(x)[i];
    __syncthreads();
    int u = blockIdx.x * 8 + warp;
    float acc[8];
    #pragma unroll
    for (int b = 0; b < 8; b++) acc[b] = 0.0f;
    const float4* wrow = reinterpret_cast<const float4*>(W + (size_t)u * V);
    #pragma unroll 1
    for (int t4 = lane; t4 < V / 4; t4 += 32) {
        float4 w = __ldcs(wrow + t4);
        int k = t4 * 4;
        #pragma unroll
        for (int b = 0; b < 8; b++) {
            float4 xv = *reinterpret_cast<const float4*>(xs + b * V + k);
            acc[b] += w.x * xv.x + w.y * xv.y + w.z * xv.z + w.w * xv.w;
        }
    }
    #pragma unroll
    for (int b = 0; b < 8; b++) {
        #pragma unroll
        for (int o = 16; o; o >>= 1) acc[b] += __shfl_xor_sync(0xffffffffu, acc[b], o);
    }
    __shared__ float sred[8][8];
    if (lane < 8) {
        float v = acc[lane] + bias[u];
        sred[warp][lane] = (ACT == 0) ? fmaxf(v, 0.0f) : sigf(v);
    }
    __syncthreads();
    if (tid < 8) {
        float s = 0.0f;
        #pragma unroll
        for (int w = 0; w < 8; w++) s += sred[w][tid];
        partials[blockIdx.x * B + tid] = s;
    }
}

// =====================================================================
// K1: per-step pre-work.
//  blocks [0,NVB)         : vertex_msg GEMV partial sums (-> g_svp[p])
//  blocks [NVB,NVB+NSPB)  : sparse Mvv @ h1  (-> g_mv)
//  block  NVB+NSPB        : color LSTM update for step-1 (uses g_svp[p^1]),
//                           then color_msg -> s_c for this step
// =====================================================================
__global__ void __launch_bounds__(256, 2) k_step_pre(
    const float* __restrict__ vmsg_w, const float* __restrict__ vmsg_b,
    const float* __restrict__ cmsg_w, const float* __restrict__ cmsg_b,
    const int* __restrict__ ncol,
    const float* __restrict__ c_whh, const float* __restrict__ c_bih,
    const float* __restrict__ c_bhh, int p, int step) {
    extern __shared__ float xs[];
    const float* h1 = g_h1[p];
    int bx = blockIdx.x, tid = threadIdx.x;
    if (bx < NVB) {
        gemv_act_block<0>(vmsg_w, vmsg_b, h1, &g_svp[p][0][0], xs);
    } else if (bx < NVB + NSPB) {
        int gid = (bx - NVB) * 256 + tid;       // = b*V + u
        int b = gid >> 11;
        int cnt = g_cnt[gid];
        const unsigned short* cp = g_cols + (size_t)gid * CAP;
        const float* hb = h1 + b * V;
        float s = 0.0f;
        for (int i = 0; i < cnt; i++) s += __ldg(hb + cp[i]);
        g_mv[gid] = s;
    } else {
        __shared__ float sv[8];
        __shared__ float chs[B][C];
        __shared__ float gates[B][4 * C];
        int warp = tid >> 5, lane = tid & 31;
        if (tid < B * C) chs[tid >> 5][tid & 31] = g_ch[tid];
        if (step > 0) {
            // reduce s_v from previous step's partials
            float s = 0.0f;
            for (int blk = lane; blk < NVB; blk += 32) s += g_svp[p ^ 1][blk][warp];
            #pragma unroll
            for (int o = 16; o; o >>= 1) s += __shfl_xor_sync(0xffffffffu, s, o);
            if (lane == 0) sv[warp] = s;
            __syncthreads();
            // color LSTM gates: gates[r] = s_v*cwm[b][r] + c_whh[r,:]·ch[b,:] + biases
            for (int idx = tid; idx < B * 4 * C; idx += 256) {
                int b = idx >> 7, r = idx & 127;
                float g = sv[b] * g_cwm[b][r] + c_bih[r] + c_bhh[r];
                #pragma unroll
                for (int c = 0; c < C; c++) g += c_whh[r * C + c] * chs[b][c];
                gates[b][r] = g;
            }
            __syncthreads();
            {
                int b = warp, j = lane;
                float gi = gates[b][j], gf = gates[b][C + j];
                float gg = gates[b][2 * C + j], go = gates[b][3 * C + j];
                float cc = sigf(gf) * g_cm[b * C + j] + sigf(gi) * tanhf(gg);
                float hh = sigf(go) * tanhf(cc);
                g_cm[b * C + j] = cc;
                g_ch[b * C + j] = hh;
                chs[b][j] = hh;
            }
            __syncthreads();
        } else {
            __syncthreads();
        }
        // color_msg + masked sum -> s_c  (one warp per batch b)
        {
            int b = warp, j = lane;
            float m = cmsg_b[j];
            #pragma unroll
            for (int c = 0; c < C; c++) m += cmsg_w[j * C + c] * chs[b][c];
            m = fmaxf(m, 0.0f);
            if (j >= ncol[b]) m = 0.0f;
            #pragma unroll
            for (int o = 16; o; o >>= 1) m += __shfl_xor_sync(0xffffffffu, m, o);
            if (j == 0) g_sc[b] = m;
        }
    }
}

// =====================================================================
// Fused dual-GEMV + LSTM cell. Warp-per-j; all 4 gate rows per warp.
// which==0: LSTM0 (x1=g_mv w/ v0_wih[:,V:], x2=g_h0[p] w/ v0_whh, + s_c*rowsum)
// which==1: LSTM1 (x1=g_h0[p^1] w/ v1_wih,  x2=g_h1[p] w/ v1_whh)
// =====================================================================
__global__ void __launch_bounds__(256, 2) k_lstm(
    const float* __restrict__ W1, int ld1, int off1,
    const float* __restrict__ W2,
    const float* __restrict__ bih, const float* __restrict__ bhh,
    int which, int p) {
    extern __shared__ float xs[];
    int tid = threadIdx.x, warp = tid >> 5, lane = tid & 31;
    int j = blockIdx.x * 8 + warp;
    const float *x1, *x2, *m_in;
    float *h_out, *m_out;
    if (which == 0) {
        x1 = g_mv; x2 = g_h0[p]; m_in = g_m0; m_out = g_m0; h_out = g_h0[p ^ 1];
    } else {
        x1 = g_h0[p ^ 1]; x2 = g_h1[p]; m_in = g_m1; m_out = g_m1; h_out = g_h1[p ^ 1];
    }

    unsigned long long acc[4][8];
    #pragma unroll
    for (int g = 0; g < 4; g++)
        #pragma unroll
        for (int b = 0; b < 8; b++) acc[g][b] = 0ull;

    #pragma unroll 1
    for (int phase = 0; phase < 2; phase++) {
        const float* x = phase ? x2 : x1;
        const float* W = phase ? W2 : W1;
        int ld = phase ? V : ld1;
        int off = phase ? 0 : off1;
        if (phase) __syncthreads();               // before overwriting xs
        for (int i = tid; i < B * V / 4; i += 256)
            reinterpret_cast<float4*>(xs)[i] = reinterpret_cast<const float4*>(x)[i];
        __syncthreads();
        const float4* wr0 = reinterpret_cast<const float4*>(W + (size_t)(0 * V + j) * ld + off);
        const float4* wr1 = reinterpret_cast<const float4*>(W + (size_t)(1 * V + j) * ld + off);
        const float4* wr2 = reinterpret_cast<const float4*>(W + (size_t)(2 * V + j) * ld + off);
        const float4* wr3 = reinterpret_cast<const float4*>(W + (size_t)(3 * V + j) * ld + off);
        #pragma unroll 1
        for (int t4 = lane; t4 < V / 4; t4 += 32) {
            F4U w0, w1, w2, w3;
            w0.f = __ldcs(wr0 + t4);
            w1.f = __ldcs(wr1 + t4);
            w2.f = __ldcs(wr2 + t4);
            w3.f = __ldcs(wr3 + t4);
            const float* xk = xs + t4 * 4;
            #pragma unroll
            for (int b = 0; b < 8; b++) {
                F4U xv;
                xv.f = *reinterpret_cast<const float4*>(xk + b * V);
                FMA2(acc[0][b], xv.u.x, w0.u.x); FMA2(acc[0][b], xv.u.y, w0.u.y);
                FMA2(acc[1][b], xv.u.x, w1.u.x); FMA2(acc[1][b], xv.u.y, w1.u.y);
                FMA2(acc[2][b], xv.u.x, w2.u.x); FMA2(acc[2][b], xv.u.y, w2.u.y);
                FMA2(acc[3][b], xv.u.x, w3.u.x); FMA2(acc[3][b], xv.u.y, w3.u.y);
            }
        }
    }

    // reduce packed halves + across lanes; lane b keeps gate g total for batch b
    float gred[4];
    #pragma unroll
    for (int g = 0; g < 4; g++) {
        gred[g] = 0.0f;
        #pragma unroll
        for (int b = 0; b < 8; b++) {
            float2 u2 = *reinterpret_cast<float2*>(&acc[g][b]);
            float s = u2.x + u2.y;
            #pragma unroll
            for (int o = 16; o; o >>= 1) s += __shfl_xor_sync(0xffffffffu, s, o);
            if (lane == b) gred[g] = s;
        }
    }
    if (lane < 8) {
        int b = lane;
        float gi = gred[0], gf = gred[1], gg = gred[2], go = gred[3];
        if (which == 0) {
            float sc = g_sc[b];
            gi += sc * g_rowsum0[j];
            gf += sc * g_rowsum0[V + j];
            gg += sc * g_rowsum0[2 * V + j];
            go += sc * g_rowsum0[3 * V + j];
        }
        gi += bih[j] + bhh[j];
        gf += bih[V + j] + bhh[V + j];
        gg += bih[2 * V + j] + bhh[2 * V + j];
        go += bih[3 * V + j] + bhh[3 * V + j];
        float cc = sigf(gf) * m_in[b * V + j] + sigf(gi) * tanhf(gg);
        float hh = sigf(go) * tanhf(cc);
        m_out[b * V + j] = cc;
        h_out[b * V + j] = hh;
    }
}

// =====================================================================
// Final vote: sigmoid GEMV partial sums, then pred = sigmoid(mean)
// =====================================================================
__global__ void __launch_bounds__(256, 2) k_vote(const float* __restrict__ W,
                                                 const float* __restrict__ bias, int p) {
    extern __shared__ float xs[];
    gemv_act_block<1>(W, bias, g_h1[p], &g_votep[0][0], xs);
}

__global__ void k_final(float* __restrict__ out) {
    int tid = threadIdx.x, warp = tid >> 5, lane = tid & 31;
    float s = 0.0f;
    for (int blk = lane; blk < NVB; blk += 32) s += g_votep[blk][warp];
    #pragma unroll
    for (int o = 16; o; o >>= 1) s += __shfl_xor_sync(0xffffffffu, s, o);
    if (lane == 0) out[warp] = sigf(s / (float)V);
}

// =====================================================================
extern "C" void kernel_launch(void* const* d_in, const int* in_sizes, int n_in,
                              void* d_out, int out_size) {
    (void)in_sizes; (void)n_in; (void)out_size;
    const float* Mvv    = (const float*)d_in[0];
    const int*   ncol   = (const int*)d_in[1];
    const float* vh0    = (const float*)d_in[2];
    const float* ch0    = (const float*)d_in[3];
    const float* v0_wih = (const float*)d_in[4];
    const float* v0_whh = (const float*)d_in[5];
    const float* v0_bih = (const float*)d_in[6];
    const float* v0_bhh = (const float*)d_in[7];
    const float* v1_wih = (const float*)d_in[8];
    const float* v1_whh = (const float*)d_in[9];
    const float* v1_bih = (const float*)d_in[10];
    const float* v1_bhh = (const float*)d_in[11];
    const float* c_wih  = (const float*)d_in[12];
    const float* c_whh  = (const float*)d_in[13];
    const float* c_bih  = (const float*)d_in[14];
    const float* c_bhh  = (const float*)d_in[15];
    const float* cmsg_w = (const float*)d_in[16];
    const float* cmsg_b = (const float*)d_in[17];
    const float* vmsg_w = (const float*)d_in[18];
    const float* vmsg_b = (const float*)d_in[19];
    const float* vote_w = (const float*)d_in[20];
    const float* vote_b = (const float*)d_in[21];
    float* out = (float*)d_out;

    const int SMEM = B * V * (int)sizeof(float);   // 65536
    cudaFuncSetAttribute(k_lstm,     cudaFuncAttributeMaxDynamicSharedMemorySize, SMEM);
    cudaFuncSetAttribute(k_step_pre, cudaFuncAttributeMaxDynamicSharedMemorySize, SMEM);
    cudaFuncSetAttribute(k_vote,     cudaFuncAttributeMaxDynamicSharedMemorySize, SMEM);

    // preprocessing (re-done every call: deterministic, no caching)
    k_init<<<64, 256>>>(vh0, ch0, c_wih, ncol);
    k_rowsum<<<1024, 256>>>(v0_wih);
    k_sparsify<<<2048, 256>>>(Mvv);

    for (int t = 0; t < TSTEPS; t++) {
        int p = t & 1;
        k_step_pre<<<NVB + NSPB + 1, 256, SMEM>>>(vmsg_w, vmsg_b, cmsg_w, cmsg_b, ncol,
                                                  c_whh, c_bih, c_bhh, p, t);
        k_lstm<<<256, 256, SMEM>>>(v0_wih, 2 * V, V, v0_whh, v0_bih, v0_bhh, 0, p);
        k_lstm<<<256, 256, SMEM>>>(v1_wih, V, 0, v1_whh, v1_bih, v1_bhh, 1, p);
    }
    // after 32 steps (even), final h1 lives in buffer 0
    k_vote<<<NVB, 256, SMEM>>>(vote_w, vote_b, 0);
    k_final<<<1, 256>>>(out);
}

// round 17
// speedup vs baseline: 1.1759x; 1.1736x over previous
#include <cuda_runtime.h>
#include <cuda_fp16.h>

// Problem constants
namespace {
constexpr int B = 8, V = 2048, C = 32, TSTEPS = 32, CAP = 128;
constexpr int NVB = 256;   // vmsg / vote GEMV blocks (8 rows each -> 2048)
constexpr int NSPB = 64;   // spmv blocks (64*256 = 16384 rows)
}

// ---- device scratch (static __device__ arrays: no runtime allocation) ----
__device__ float g_h0[2][B * V];
__device__ float g_h1[2][B * V];
__device__ float g_m0[B * V];
__device__ float g_m1[B * V];
__device__ float g_ch[B * C];
__device__ float g_cm[B * C];
__device__ float g_mv[B * V];          // muled_v
__device__ float g_sc[B];              // s_c scalar per batch
__device__ float g_svp[2][NVB][B];     // vertex_msg partial sums (double-buffered)
__device__ float g_votep[NVB][B];      // vote partial sums
__device__ float g_rowsum0[4 * V];     // rowsum of v0_wih[:, :V] (exact fp32)
__device__ float g_cwm[B][4 * C];      // mask @ c_wih^T per batch
__device__ unsigned short g_cols[(size_t)B * V * CAP];
__device__ int g_cnt[B * V];

// fp16 weight copies (converted once per launch)
__device__ __half g_w0x[(size_t)4 * V * V];   // v0_wih columns [V,2V)
__device__ __half g_w0h[(size_t)4 * V * V];   // v0_whh
__device__ __half g_w1x[(size_t)4 * V * V];   // v1_wih
__device__ __half g_w1h[(size_t)4 * V * V];   // v1_whh
__device__ __half g_wv[(size_t)V * V];        // vmsg_w
__device__ __half g_wvt[(size_t)V * V];       // vote_w

__device__ __forceinline__ float sigf(float x) { return 1.0f / (1.0f + expf(-x)); }

// packed 2xfp32 FMA: d = a*b + d elementwise on packed halves
#define FMA2(d, a, b_) asm("fma.rn.f32x2 %0, %1, %2, %0;" : "+l"(d) : "l"(a), "l"(b_))

union F4U { float4 f; ulonglong2 u; };
union F2U { float2 f; unsigned long long u; };

// half2 (bit pattern in uint) -> packed f32x2 bit pattern (ull)
__device__ __forceinline__ unsigned long long h2f2(unsigned int h2bits) {
    __half2 h = *reinterpret_cast<const __half2*>(&h2bits);
    F2U r; r.f = __half22float2(h);
    return r.u;
}
__device__ __forceinline__ float2 h2tof(unsigned int h2bits) {
    __half2 h = *reinterpret_cast<const __half2*>(&h2bits);
    return __half22float2(h);
}

// =====================================================================
// Preprocessing kernels
// =====================================================================
__global__ void k_init(const float* __restrict__ vh0, const float* __restrict__ ch0,
                       const float* __restrict__ c_wih, const int* __restrict__ ncol) {
    int tid = blockIdx.x * 256 + threadIdx.x;   // exactly B*V = 16384 threads
    g_h0[0][tid] = vh0[tid];
    g_h1[0][tid] = vh0[B * V + tid];
    g_m0[tid] = 0.0f;
    g_m1[tid] = 0.0f;
    if (tid < B * C) { g_ch[tid] = ch0[tid]; g_cm[tid] = 0.0f; }
    if (tid < B * 4 * C) {
        int b = tid >> 7, r = tid & 127;
        int nc = ncol[b];
        float s = 0.0f;
        for (int c = 0; c < nc; c++) s += c_wih[r * C + c];
        g_cwm[b][r] = s;
    }
}

// fp32 -> fp16 weight conversion; cols = V, row stride ld, column offset off
__global__ void k_cvt(const float* __restrict__ src, __half* __restrict__ dst,
                      int total4, int ld, int off) {
    int i = blockIdx.x * 256 + threadIdx.x;
    if (i >= total4) return;
    int e = i * 4;
    int r = e >> 11;            // /V
    int c = e & (V - 1);
    float4 v = *reinterpret_cast<const float4*>(src + (size_t)r * ld + off + c);
    union { __half2 h[2]; uint2 u; } pk;
    pk.h[0] = __floats2half2_rn(v.x, v.y);
    pk.h[1] = __floats2half2_rn(v.z, v.w);
    *reinterpret_cast<uint2*>(dst + e) = pk.u;
}

// rowsum over first V columns of v0_wih (row stride 2V); one warp per row
__global__ void k_rowsum(const float* __restrict__ w) {
    int r = blockIdx.x * 8 + (threadIdx.x >> 5);
    int lane = threadIdx.x & 31;
    const float4* row = reinterpret_cast<const float4*>(w + (size_t)r * (2 * V));
    float s = 0.0f;
    for (int i = lane; i < V / 4; i += 32) {
        float4 v = __ldcs(row + i);
        s += v.x + v.y + v.z + v.w;
    }
    #pragma unroll
    for (int o = 16; o; o >>= 1) s += __shfl_xor_sync(0xffffffffu, s, o);
    if (lane == 0) g_rowsum0[r] = s;
}

// sparsify Mvv: one warp per (b,u) row; deterministic in-order compaction
__global__ void k_sparsify(const float* __restrict__ Mvv) {
    int row = blockIdx.x * 8 + (threadIdx.x >> 5);   // 0..16383
    int lane = threadIdx.x & 31;
    const float* p = Mvv + (size_t)row * V;
    int cnt = 0;
    for (int i = 0; i < V / 32; i++) {
        float v = p[i * 32 + lane];
        unsigned m = __ballot_sync(0xffffffffu, v != 0.0f);
        if (v != 0.0f) {
            int pos = cnt + __popc(m & ((1u << lane) - 1u));
            if (pos < CAP) g_cols[(size_t)row * CAP + pos] = (unsigned short)(i * 32 + lane);
        }
        cnt += __popc(m);
    }
    if (lane == 0) g_cnt[row] = min(cnt, CAP);
}

// =====================================================================
// fp16 GEMV + activation + per-block partial sum (vmsg & vote).
// No smem staging: x (64KB) is L1/L2-hot, read via __ldg. Warp-per-row,
// 8 rows per block. 1-deep software pipeline on the weight loads.
// ACT: 0 = relu, 1 = sigmoid.
// =====================================================================
template <int ACT>
__device__ __forceinline__ void gemv_h16_block(const __half* __restrict__ W,
                                               const float* __restrict__ bias,
                                               const float* __restrict__ x,
                                               float* __restrict__ partials) {
    int tid = threadIdx.x, warp = tid >> 5, lane = tid & 31;
    int u = blockIdx.x * 8 + warp;
    float acc[8];
    #pragma unroll
    for (int b = 0; b < 8; b++) acc[b] = 0.0f;
    const uint2* wrow = reinterpret_cast<const uint2*>(W + (size_t)u * V);
    uint2 cw = __ldcs(wrow + lane);
    #pragma unroll 1
    for (int t4 = lane; t4 < V / 4; t4 += 32) {
        int nx = t4 + 32;
        uint2 nw = (nx < V / 4) ? __ldcs(wrow + nx) : make_uint2(0u, 0u);
        float2 wa = h2tof(cw.x), wb = h2tof(cw.y);
        int k = t4 * 4;
        #pragma unroll
        for (int b = 0; b < 8; b++) {
            float4 xv = __ldg(reinterpret_cast<const float4*>(x + b * V + k));
            acc[b] += wa.x * xv.x + wa.y * xv.y + wb.x * xv.z + wb.y * xv.w;
        }
        cw = nw;
    }
    #pragma unroll
    for (int b = 0; b < 8; b++) {
        #pragma unroll
        for (int o = 16; o; o >>= 1) acc[b] += __shfl_xor_sync(0xffffffffu, acc[b], o);
    }
    __shared__ float sred[8][8];
    if (lane < 8) {
        float v = acc[lane] + bias[u];
        sred[warp][lane] = (ACT == 0) ? fmaxf(v, 0.0f) : sigf(v);
    }
    __syncthreads();
    if (tid < 8) {
        float s = 0.0f;
        #pragma unroll
        for (int w = 0; w < 8; w++) s += sred[w][tid];
        partials[blockIdx.x * B + tid] = s;
    }
}

// =====================================================================
// K1: per-step pre-work.
//  blocks [0,NVB)         : vertex_msg fp16 GEMV partial sums (-> g_svp[p])
//  blocks [NVB,NVB+NSPB)  : sparse Mvv @ h1  (-> g_mv)
//  block  NVB+NSPB        : color LSTM update for step-1, then s_c
// =====================================================================
__global__ void __launch_bounds__(256) k_step_pre(
    const float* __restrict__ vmsg_b,
    const float* __restrict__ cmsg_w, const float* __restrict__ cmsg_b,
    const int* __restrict__ ncol,
    const float* __restrict__ c_whh, const float* __restrict__ c_bih,
    const float* __restrict__ c_bhh, int p, int step) {
    const float* h1 = g_h1[p];
    int bx = blockIdx.x, tid = threadIdx.x;
    if (bx < NVB) {
        gemv_h16_block<0>(g_wv, vmsg_b, h1, &g_svp[p][0][0]);
    } else if (bx < NVB + NSPB) {
        int gid = (bx - NVB) * 256 + tid;       // = b*V + u
        int b = gid >> 11;
        int cnt = g_cnt[gid];
        const unsigned short* cp = g_cols + (size_t)gid * CAP;
        const float* hb = h1 + b * V;
        float s = 0.0f;
        #pragma unroll 4
        for (int i = 0; i < cnt; i++) s += __ldg(hb + cp[i]);
        g_mv[gid] = s;
    } else {
        __shared__ float sv[8];
        __shared__ float chs[B][C];
        __shared__ float gates[B][4 * C];
        int warp = tid >> 5, lane = tid & 31;
        if (tid < B * C) chs[tid >> 5][tid & 31] = g_ch[tid];
        if (step > 0) {
            // reduce s_v from previous step's partials
            float s = 0.0f;
            for (int blk = lane; blk < NVB; blk += 32) s += g_svp[p ^ 1][blk][warp];
            #pragma unroll
            for (int o = 16; o; o >>= 1) s += __shfl_xor_sync(0xffffffffu, s, o);
            if (lane == 0) sv[warp] = s;
            __syncthreads();
            // color LSTM gates (fp32 exact, tiny)
            for (int idx = tid; idx < B * 4 * C; idx += 256) {
                int b = idx >> 7, r = idx & 127;
                float g = sv[b] * g_cwm[b][r] + c_bih[r] + c_bhh[r];
                #pragma unroll
                for (int c = 0; c < C; c++) g += c_whh[r * C + c] * chs[b][c];
                gates[b][r] = g;
            }
            __syncthreads();
            {
                int b = warp, j = lane;
                float gi = gates[b][j], gf = gates[b][C + j];
                float gg = gates[b][2 * C + j], go = gates[b][3 * C + j];
                float cc = sigf(gf) * g_cm[b * C + j] + sigf(gi) * tanhf(gg);
                float hh = sigf(go) * tanhf(cc);
                g_cm[b * C + j] = cc;
                g_ch[b * C + j] = hh;
                chs[b][j] = hh;
            }
            __syncthreads();
        } else {
            __syncthreads();
        }
        // color_msg + masked sum -> s_c (one warp per batch b)
        {
            int b = warp, j = lane;
            float m = cmsg_b[j];
            #pragma unroll
            for (int c = 0; c < C; c++) m += cmsg_w[j * C + c] * chs[b][c];
            m = fmaxf(m, 0.0f);
            if (j >= ncol[b]) m = 0.0f;
            #pragma unroll
            for (int o = 16; o; o >>= 1) m += __shfl_xor_sync(0xffffffffu, m, o);
            if (j == 0) g_sc[b] = m;
        }
    }
}

// =====================================================================
// Fused dual-GEMV + LSTM cell, fp16 weights, f32x2 accumulation.
// Warp-per-j; all 4 gate rows per warp; 1-deep SW pipeline on weight loads.
// which==0: LSTM0 (x1=g_mv w/ g_w0x, x2=g_h0[p] w/ g_w0h, + s_c*rowsum)
// which==1: LSTM1 (x1=g_h0[p^1] w/ g_w1x, x2=g_h1[p] w/ g_w1h)
// =====================================================================
__global__ void __launch_bounds__(256, 2) k_lstm(
    const float* __restrict__ bih, const float* __restrict__ bhh,
    int which, int p) {
    extern __shared__ float xs[];
    int tid = threadIdx.x, warp = tid >> 5, lane = tid & 31;
    int j = blockIdx.x * 8 + warp;
    const float *x1, *x2, *m_in;
    float *h_out, *m_out;
    const __half *W1, *W2;
    if (which == 0) {
        x1 = g_mv; x2 = g_h0[p]; m_in = g_m0; m_out = g_m0; h_out = g_h0[p ^ 1];
        W1 = g_w0x; W2 = g_w0h;
    } else {
        x1 = g_h0[p ^ 1]; x2 = g_h1[p]; m_in = g_m1; m_out = g_m1; h_out = g_h1[p ^ 1];
        W1 = g_w1x; W2 = g_w1h;
    }

    unsigned long long acc[4][8];
    #pragma unroll
    for (int g = 0; g < 4; g++)
        #pragma unroll
        for (int b = 0; b < 8; b++) acc[g][b] = 0ull;

    #pragma unroll 1
    for (int phase = 0; phase < 2; phase++) {
        const float* x = phase ? x2 : x1;
        const __half* W = phase ? W2 : W1;
        if (phase) __syncthreads();               // before overwriting xs
        for (int i = tid; i < B * V / 4; i += 256)
            reinterpret_cast<float4*>(xs)[i] = reinterpret_cast<const float4*>(x)[i];
        __syncthreads();
        const uint2* wr0 = reinterpret_cast<const uint2*>(W + (size_t)(0 * V + j) * V);
        const uint2* wr1 = reinterpret_cast<const uint2*>(W + (size_t)(1 * V + j) * V);
        const uint2* wr2 = reinterpret_cast<const uint2*>(W + (size_t)(2 * V + j) * V);
        const uint2* wr3 = reinterpret_cast<const uint2*>(W + (size_t)(3 * V + j) * V);
        uint2 c0 = __ldcs(wr0 + lane);
        uint2 c1 = __ldcs(wr1 + lane);
        uint2 c2 = __ldcs(wr2 + lane);
        uint2 c3 = __ldcs(wr3 + lane);
        #pragma unroll 1
        for (int t4 = lane; t4 < V / 4; t4 += 32) {
            int nx = t4 + 32;
            uint2 n0, n1, n2, n3;
            if (nx < V / 4) {
                n0 = __ldcs(wr0 + nx); n1 = __ldcs(wr1 + nx);
                n2 = __ldcs(wr2 + nx); n3 = __ldcs(wr3 + nx);
            } else {
                n0 = n1 = n2 = n3 = make_uint2(0u, 0u);
            }
            unsigned long long w0a = h2f2(c0.x), w0b = h2f2(c0.y);
            unsigned long long w1a = h2f2(c1.x), w1b = h2f2(c1.y);
            unsigned long long w2a = h2f2(c2.x), w2b = h2f2(c2.y);
            unsigned long long w3a = h2f2(c3.x), w3b = h2f2(c3.y);
            const float* xk = xs + t4 * 4;
            #pragma unroll
            for (int b = 0; b < 8; b++) {
                F4U xv;
                xv.f = *reinterpret_cast<const float4*>(xk + b * V);
                FMA2(acc[0][b], xv.u.x, w0a); FMA2(acc[0][b], xv.u.y, w0b);
                FMA2(acc[1][b], xv.u.x, w1a); FMA2(acc[1][b], xv.u.y, w1b);
                FMA2(acc[2][b], xv.u.x, w2a); FMA2(acc[2][b], xv.u.y, w2b);
                FMA2(acc[3][b], xv.u.x, w3a); FMA2(acc[3][b], xv.u.y, w3b);
            }
            c0 = n0; c1 = n1; c2 = n2; c3 = n3;
        }
    }

    // reduce packed halves + across lanes; lane b keeps gate g total for batch b
    float gred[4];
    #pragma unroll
    for (int g = 0; g < 4; g++) {
        gred[g] = 0.0f;
        #pragma unroll
        for (int b = 0; b < 8; b++) {
            float2 u2 = *reinterpret_cast<float2*>(&acc[g][b]);
            float s = u2.x + u2.y;
            #pragma unroll
            for (int o = 16; o; o >>= 1) s += __shfl_xor_sync(0xffffffffu, s, o);
            if (lane == b) gred[g] = s;
        }
    }
    if (lane < 8) {
        int b = lane;
        float gi = gred[0], gf = gred[1], gg = gred[2], go = gred[3];
        if (which == 0) {
            float sc = g_sc[b];
            gi += sc * g_rowsum0[j];
            gf += sc * g_rowsum0[V + j];
            gg += sc * g_rowsum0[2 * V + j];
            go += sc * g_rowsum0[3 * V + j];
        }
        gi += bih[j] + bhh[j];
        gf += bih[V + j] + bhh[V + j];
        gg += bih[2 * V + j] + bhh[2 * V + j];
        go += bih[3 * V + j] + bhh[3 * V + j];
        float cc = sigf(gf) * m_in[b * V + j] + sigf(gi) * tanhf(gg);
        float hh = sigf(go) * tanhf(cc);
        m_out[b * V + j] = cc;
        h_out[b * V + j] = hh;
    }
}

// =====================================================================
// Final vote: sigmoid GEMV partial sums, then pred = sigmoid(mean)
// =====================================================================
__global__ void __launch_bounds__(256) k_vote(const float* __restrict__ bias, int p) {
    gemv_h16_block<1>(g_wvt, bias, g_h1[p], &g_votep[0][0]);
}

__global__ void k_final(float* __restrict__ out) {
    int tid = threadIdx.x, warp = tid >> 5, lane = tid & 31;
    float s = 0.0f;
    for (int blk = lane; blk < NVB; blk += 32) s += g_votep[blk][warp];
    #pragma unroll
    for (int o = 16; o; o >>= 1) s += __shfl_xor_sync(0xffffffffu, s, o);
    if (lane == 0) out[warp] = sigf(s / (float)V);
}

// =====================================================================
extern "C" void kernel_launch(void* const* d_in, const int* in_sizes, int n_in,
                              void* d_out, int out_size) {
    (void)in_sizes; (void)n_in; (void)out_size;
    const float* Mvv    = (const float*)d_in[0];
    const int*   ncol   = (const int*)d_in[1];
    const float* vh0    = (const float*)d_in[2];
    const float* ch0    = (const float*)d_in[3];
    const float* v0_wih = (const float*)d_in[4];
    const float* v0_whh = (const float*)d_in[5];
    const float* v0_bih = (const float*)d_in[6];
    const float* v0_bhh = (const float*)d_in[7];
    const float* v1_wih = (const float*)d_in[8];
    const float* v1_whh = (const float*)d_in[9];
    const float* v1_bih = (const float*)d_in[10];
    const float* v1_bhh = (const float*)d_in[11];
    const float* c_wih  = (const float*)d_in[12];
    const float* c_whh  = (const float*)d_in[13];
    const float* c_bih  = (const float*)d_in[14];
    const float* c_bhh  = (const float*)d_in[15];
    const float* cmsg_w = (const float*)d_in[16];
    const float* cmsg_b = (const float*)d_in[17];
    const float* vmsg_w = (const float*)d_in[18];
    const float* vmsg_b = (const float*)d_in[19];
    const float* vote_w = (const float*)d_in[20];
    const float* vote_b = (const float*)d_in[21];
    float* out = (float*)d_out;

    const int SMEM = B * V * (int)sizeof(float);   // 65536
    cudaFuncSetAttribute(k_lstm, cudaFuncAttributeMaxDynamicSharedMemorySize, SMEM);

    // fetch device-scratch addresses for the fp16 weight targets
    __half *w0x, *w0h, *w1x, *w1h, *wv, *wvt;
    cudaGetSymbolAddress((void**)&w0x, g_w0x);
    cudaGetSymbolAddress((void**)&w0h, g_w0h);
    cudaGetSymbolAddress((void**)&w1x, g_w1x);
    cudaGetSymbolAddress((void**)&w1h, g_w1h);
    cudaGetSymbolAddress((void**)&wv,  g_wv);
    cudaGetSymbolAddress((void**)&wvt, g_wvt);

    // preprocessing (re-done every call: deterministic, no caching)
    k_init<<<64, 256>>>(vh0, ch0, c_wih, ncol);
    k_rowsum<<<1024, 256>>>(v0_wih);
    k_sparsify<<<2048, 256>>>(Mvv);
    {
        const int big4 = 4 * V * V / 4;   // 4.19M quads
        const int sml4 = V * V / 4;       // 1.05M quads
        k_cvt<<<(big4 + 255) / 256, 256>>>(v0_wih, w0x, big4, 2 * V, V);
        k_cvt<<<(big4 + 255) / 256, 256>>>(v0_whh, w0h, big4, V, 0);
        k_cvt<<<(big4 + 255) / 256, 256>>>(v1_wih, w1x, big4, V, 0);
        k_cvt<<<(big4 + 255) / 256, 256>>>(v1_whh, w1h, big4, V, 0);
        k_cvt<<<(sml4 + 255) / 256, 256>>>(vmsg_w, wv, sml4, V, 0);
        k_cvt<<<(sml4 + 255) / 256, 256>>>(vote_w, wvt, sml4, V, 0);
    }

    for (int t = 0; t < TSTEPS; t++) {
        int p = t & 1;
        k_step_pre<<<NVB + NSPB + 1, 256>>>(vmsg_b, cmsg_w, cmsg_b, ncol,
                                            c_whh, c_bih, c_bhh, p, t);
        k_lstm<<<256, 256, SMEM>>>(v0_bih, v0_bhh, 0, p);
        k_lstm<<<256, 256, SMEM>>>(v1_bih, v1_bhh, 1, p);
    }
    // after 32 steps (even), final h1 lives in buffer 0
    k_vote<<<NVB, 256>>>(vote_b, 0);
    k_final<<<1, 256>>>(out);
}